// round 1
// baseline (speedup 1.0000x reference)
#include <cuda_runtime.h>
#include <mma.h>
#include <math.h>

using namespace nvcuda;

#define NN 100000
#define DD 512
#define EE 3200000

// ---------------- scratch (__device__ globals: no allocation allowed) ----------
__device__ float g_support[(size_t)NN * DD];
__device__ float g_trans[(size_t)NN * DD];
__device__ float g_gate[(size_t)NN * DD];
__device__ int   g_deg[NN];
__device__ int   g_cursor[NN];
__device__ int   g_rowptr[NN + 1];
__device__ int   g_ecol[EE];
__device__ float g_eval[EE];

__device__ __forceinline__ float sigmoidf_(float x) {
    return 1.0f / (1.0f + __expf(-x));
}

// ---------------- CSR build ---------------------------------------------------
__global__ void k_init() {
    int i = blockIdx.x * blockDim.x + threadIdx.x;
    if (i < NN) { g_deg[i] = 0; g_cursor[i] = 0; }
}

__global__ void k_hist(const int* __restrict__ erow) {
    int e = blockIdx.x * blockDim.x + threadIdx.x;
    if (e < EE) atomicAdd(&g_deg[erow[e]], 1);
}

// single-block exclusive scan of g_deg -> g_rowptr (N=100000, 1024 threads)
__global__ void k_scan() {
    __shared__ int s[1024];
    const int CH = (NN + 1023) / 1024;  // 98
    int t = threadIdx.x;
    int start = t * CH;
    int end = start + CH; if (end > NN) end = NN;
    int sum = 0;
    for (int i = start; i < end; i++) sum += g_deg[i];
    s[t] = sum;
    __syncthreads();
    // Hillis-Steele inclusive scan
    for (int off = 1; off < 1024; off <<= 1) {
        int v = (t >= off) ? s[t - off] : 0;
        __syncthreads();
        s[t] += v;
        __syncthreads();
    }
    int excl = s[t] - sum;
    for (int i = start; i < end; i++) {
        g_rowptr[i] = excl;
        excl += g_deg[i];
    }
    if (t == 1023) g_rowptr[NN] = s[1023];
}

__global__ void k_scatter(const int* __restrict__ erow,
                          const int* __restrict__ ecol,
                          const float* __restrict__ eval) {
    int e = blockIdx.x * blockDim.x + threadIdx.x;
    if (e < EE) {
        int r = erow[e];
        int pos = g_rowptr[r] + atomicAdd(&g_cursor[r], 1);
        g_ecol[pos] = ecol[e];
        g_eval[pos] = eval[e];
    }
}

// ---------------- fused triple-projection GEMM (tf32 wmma) --------------------
// grid: (DD/64, ceil(N/64), 3)   block: 128 threads (4 warps, each 32x32)
#define BM 64
#define BN 64
#define BK 32

__global__ void k_gemm(const float* __restrict__ X,
                       const float* __restrict__ W1,
                       const float* __restrict__ W2,
                       const float* __restrict__ W3,
                       const float* __restrict__ B2,
                       const float* __restrict__ B3) {
    __shared__ float sA[BM][BK + 4];
    __shared__ float sB[BK][BN + 4];
    __shared__ float sC[BM][BN + 4];

    const int z = blockIdx.z;
    const float* W = (z == 0) ? W1 : ((z == 1) ? W2 : W3);
    const int m0 = blockIdx.y * BM;
    const int n0 = blockIdx.x * BN;
    const int tid = threadIdx.x;
    const int warp = tid >> 5;
    const int wm = (warp & 1) * 32;
    const int wn = (warp >> 1) * 32;

    wmma::fragment<wmma::accumulator, 16, 16, 8, float> fc[2][2];
    #pragma unroll
    for (int i = 0; i < 2; i++)
        #pragma unroll
        for (int j = 0; j < 2; j++)
            wmma::fill_fragment(fc[i][j], 0.0f);

    for (int k0 = 0; k0 < DD; k0 += BK) {
        // stage A tile 64x32 (tf32-rounded), 4 float4 per thread
        #pragma unroll
        for (int i = 0; i < 4; i++) {
            int idx = tid + i * 128;        // 0..511 float4s
            int row = idx >> 3;             // 0..63
            int col = (idx & 7) * 4;        // 0..28
            int gr = m0 + row;
            float4 v = make_float4(0.f, 0.f, 0.f, 0.f);
            if (gr < NN)
                v = *(const float4*)&X[(size_t)gr * DD + k0 + col];
            sA[row][col + 0] = wmma::__float_to_tf32(v.x);
            sA[row][col + 1] = wmma::__float_to_tf32(v.y);
            sA[row][col + 2] = wmma::__float_to_tf32(v.z);
            sA[row][col + 3] = wmma::__float_to_tf32(v.w);
        }
        // stage B tile 32x64
        #pragma unroll
        for (int i = 0; i < 4; i++) {
            int idx = tid + i * 128;        // 0..511 float4s
            int row = idx >> 4;             // 0..31
            int col = (idx & 15) * 4;       // 0..60
            float4 v = *(const float4*)&W[(size_t)(k0 + row) * DD + n0 + col];
            sB[row][col + 0] = wmma::__float_to_tf32(v.x);
            sB[row][col + 1] = wmma::__float_to_tf32(v.y);
            sB[row][col + 2] = wmma::__float_to_tf32(v.z);
            sB[row][col + 3] = wmma::__float_to_tf32(v.w);
        }
        __syncthreads();

        #pragma unroll
        for (int kk = 0; kk < BK; kk += 8) {
            wmma::fragment<wmma::matrix_a, 16, 16, 8, wmma::precision::tf32, wmma::row_major> fa[2];
            wmma::fragment<wmma::matrix_b, 16, 16, 8, wmma::precision::tf32, wmma::row_major> fb[2];
            #pragma unroll
            for (int i = 0; i < 2; i++)
                wmma::load_matrix_sync(fa[i], &sA[wm + 16 * i][kk], BK + 4);
            #pragma unroll
            for (int j = 0; j < 2; j++)
                wmma::load_matrix_sync(fb[j], &sB[kk][wn + 16 * j], BN + 4);
            #pragma unroll
            for (int i = 0; i < 2; i++)
                #pragma unroll
                for (int j = 0; j < 2; j++)
                    wmma::mma_sync(fc[i][j], fa[i], fb[j], fc[i][j]);
        }
        __syncthreads();
    }

    // epilogue via smem
    #pragma unroll
    for (int i = 0; i < 2; i++)
        #pragma unroll
        for (int j = 0; j < 2; j++)
            wmma::store_matrix_sync(&sC[wm + 16 * i][wn + 16 * j], fc[i][j],
                                    BN + 4, wmma::mem_row_major);
    __syncthreads();

    float* dst = (z == 0) ? g_support : ((z == 1) ? g_trans : g_gate);
    const float* bias = (z == 1) ? B2 : B3;
    #pragma unroll
    for (int i = 0; i < 8; i++) {
        int idx = tid + i * 128;            // 0..1023 float4s
        int row = idx >> 4;                 // 0..63
        int col = (idx & 15) * 4;           // 0..60
        int gr = m0 + row;
        if (gr < NN) {
            float4 v;
            v.x = sC[row][col + 0];
            v.y = sC[row][col + 1];
            v.z = sC[row][col + 2];
            v.w = sC[row][col + 3];
            if (z == 1) {
                v.x += bias[n0 + col + 0];
                v.y += bias[n0 + col + 1];
                v.z += bias[n0 + col + 2];
                v.w += bias[n0 + col + 3];
            } else if (z == 2) {
                v.x = sigmoidf_(v.x + bias[n0 + col + 0]);
                v.y = sigmoidf_(v.y + bias[n0 + col + 1]);
                v.z = sigmoidf_(v.z + bias[n0 + col + 2]);
                v.w = sigmoidf_(v.w + bias[n0 + col + 3]);
            }
            *(float4*)&dst[(size_t)gr * DD + n0 + col] = v;
        }
    }
}

// ---------------- warp-per-row SpMM + fused relu/gated combine ----------------
__global__ void k_spmm(const float* __restrict__ b1, float* __restrict__ out) {
    int gw = (blockIdx.x * blockDim.x + threadIdx.x) >> 5;
    int lane = threadIdx.x & 31;
    if (gw >= NN) return;
    int s = g_rowptr[gw];
    int e = g_rowptr[gw + 1];

    float4 a0 = make_float4(0.f, 0.f, 0.f, 0.f);
    float4 a1 = a0, a2 = a0, a3 = a0;
    const float4* sup = (const float4*)g_support;

    for (int i = s; i < e; i++) {
        int c = __ldg(&g_ecol[i]);
        float v = __ldg(&g_eval[i]);
        const float4* p = sup + (size_t)c * (DD / 4);
        float4 s0 = p[lane];
        float4 s1 = p[lane + 32];
        float4 s2 = p[lane + 64];
        float4 s3 = p[lane + 96];
        a0.x += v * s0.x; a0.y += v * s0.y; a0.z += v * s0.z; a0.w += v * s0.w;
        a1.x += v * s1.x; a1.y += v * s1.y; a1.z += v * s1.z; a1.w += v * s1.w;
        a2.x += v * s2.x; a2.y += v * s2.y; a2.z += v * s2.z; a2.w += v * s2.w;
        a3.x += v * s3.x; a3.y += v * s3.y; a3.z += v * s3.z; a3.w += v * s3.w;
    }

    const float4* bv = (const float4*)b1;
    const float4* tp = ((const float4*)g_trans) + (size_t)gw * (DD / 4);
    const float4* gp = ((const float4*)g_gate) + (size_t)gw * (DD / 4);
    float4* op = ((float4*)out) + (size_t)gw * (DD / 4);

#define FIN(acc, IDX)                                                    \
    {                                                                    \
        int idx = (IDX);                                                 \
        float4 bb = bv[idx];                                             \
        float4 t = tp[idx];                                              \
        float4 g = gp[idx];                                              \
        float4 r;                                                        \
        float rx = fmaxf(acc.x + bb.x, 0.f);                             \
        float ry = fmaxf(acc.y + bb.y, 0.f);                             \
        float rz = fmaxf(acc.z + bb.z, 0.f);                             \
        float rw = fmaxf(acc.w + bb.w, 0.f);                             \
        r.x = t.x + g.x * (rx - t.x);                                    \
        r.y = t.y + g.y * (ry - t.y);                                    \
        r.z = t.z + g.z * (rz - t.z);                                    \
        r.w = t.w + g.w * (rw - t.w);                                    \
        op[idx] = r;                                                     \
    }

    FIN(a0, lane);
    FIN(a1, lane + 32);
    FIN(a2, lane + 64);
    FIN(a3, lane + 96);
#undef FIN
}

// ---------------- launch -------------------------------------------------------
extern "C" void kernel_launch(void* const* d_in, const int* in_sizes, int n_in,
                              void* d_out, int out_size) {
    const float* x   = (const float*)d_in[0];
    const float* w1  = (const float*)d_in[1];
    const float* w2  = (const float*)d_in[2];
    const float* w3  = (const float*)d_in[3];
    const float* b1  = (const float*)d_in[4];
    const float* b2  = (const float*)d_in[5];
    const float* b3  = (const float*)d_in[6];
    const int*   er  = (const int*)d_in[7];
    const int*   ec  = (const int*)d_in[8];
    const float* ev  = (const float*)d_in[9];
    float* out = (float*)d_out;

    // CSR build
    k_init<<<(NN + 255) / 256, 256>>>();
    k_hist<<<(EE + 255) / 256, 256>>>(er);
    k_scan<<<1, 1024>>>();
    k_scatter<<<(EE + 255) / 256, 256>>>(er, ec, ev);

    // three projections (support / trans / gate), tf32 tensor cores
    dim3 ggrid(DD / BN, (NN + BM - 1) / BM, 3);
    k_gemm<<<ggrid, 128>>>(x, w1, w2, w3, b2, b3);

    // atomic-free SpMM + fused relu + gated combine
    int warps_per_block = 8;
    int blocks = (NN + warps_per_block - 1) / warps_per_block;
    k_spmm<<<blocks, warps_per_block * 32>>>(b1, out);
}

// round 3
// speedup vs baseline: 2.7815x; 2.7815x over previous
#include <cuda_runtime.h>
#include <cuda_fp16.h>
#include <cstdint>
#include <math.h>

#define NN 100000
#define DD 512
#define EE 3200000

// ---------------- scratch (__device__ globals) --------------------------------
__device__ __half g_suph[(size_t)NN * DD];   // support in fp16 (gathered a lot)
__device__ float  g_trans[(size_t)NN * DD];
__device__ float  g_gate[(size_t)NN * DD];
__device__ __half g_xh[(size_t)NN * DD];     // x in fp16
__device__ __half g_wh[3 * DD * DD];         // weights in fp16, [z][k][n]
__device__ int    g_deg[NN];
__device__ int    g_cursor[NN];
__device__ int    g_rowptr[NN + 1];
__device__ int2   g_epack[EE];               // packed (col, val bits)

__device__ __forceinline__ uint32_t smem_to_u32(const void* smem_ptr) {
    uint32_t addr;
    asm("{ .reg .u64 tmp; cvta.to.shared.u64 tmp, %1; cvt.u32.u64 %0, tmp; }"
        : "=r"(addr) : "l"(smem_ptr));
    return addr;
}

__device__ __forceinline__ float sigmoidf_(float x) {
    return 1.0f / (1.0f + __expf(-x));
}

// ---------------- CSR build ---------------------------------------------------
__global__ void k_init() {
    int i = blockIdx.x * blockDim.x + threadIdx.x;
    if (i < NN) { g_deg[i] = 0; g_cursor[i] = 0; }
}

__global__ void k_hist(const int* __restrict__ erow) {
    int e = blockIdx.x * blockDim.x + threadIdx.x;
    if (e < EE) atomicAdd(&g_deg[erow[e]], 1);
}

__global__ void k_scan() {
    __shared__ int s[1024];
    const int CH = (NN + 1023) / 1024;
    int t = threadIdx.x;
    int start = t * CH;
    int end = start + CH; if (end > NN) end = NN;
    int sum = 0;
    for (int i = start; i < end; i++) sum += g_deg[i];
    s[t] = sum;
    __syncthreads();
    for (int off = 1; off < 1024; off <<= 1) {
        int v = (t >= off) ? s[t - off] : 0;
        __syncthreads();
        s[t] += v;
        __syncthreads();
    }
    int excl = s[t] - sum;
    for (int i = start; i < end; i++) {
        g_rowptr[i] = excl;
        excl += g_deg[i];
    }
    if (t == 1023) g_rowptr[NN] = s[1023];
}

__global__ void k_scatter(const int* __restrict__ erow,
                          const int* __restrict__ ecol,
                          const float* __restrict__ eval) {
    int e = blockIdx.x * blockDim.x + threadIdx.x;
    if (e < EE) {
        int r = erow[e];
        int pos = g_rowptr[r] + atomicAdd(&g_cursor[r], 1);
        g_epack[pos] = make_int2(ecol[e], __float_as_int(eval[e]));
    }
}

// ---------------- fp32 -> fp16 conversions ------------------------------------
__global__ void k_xh(const float* __restrict__ x) {
    int idx = blockIdx.x * blockDim.x + threadIdx.x;   // over N*DD/4
    if (idx < NN * (DD / 4)) {
        float4 v = *(const float4*)&x[(size_t)idx * 4];
        __half2 h[2];
        h[0] = __float22half2_rn(make_float2(v.x, v.y));
        h[1] = __float22half2_rn(make_float2(v.z, v.w));
        *(uint2*)&g_xh[(size_t)idx * 4] = *(uint2*)h;
    }
}

__global__ void k_wh(const float* __restrict__ w1,
                     const float* __restrict__ w2,
                     const float* __restrict__ w3) {
    int idx = blockIdx.x * blockDim.x + threadIdx.x;   // over 3*DD*DD/4
    if (idx < 3 * DD * DD / 4) {
        int z = idx / (DD * DD / 4);
        int off = idx - z * (DD * DD / 4);
        const float* w = (z == 0) ? w1 : ((z == 1) ? w2 : w3);
        float4 v = *(const float4*)&w[(size_t)off * 4];
        __half2 h[2];
        h[0] = __float22half2_rn(make_float2(v.x, v.y));
        h[1] = __float22half2_rn(make_float2(v.z, v.w));
        *(uint2*)&g_wh[(size_t)z * DD * DD + (size_t)off * 4] = *(uint2*)h;
    }
}

// ---------------- fp16 mma.sync GEMM ------------------------------------------
// grid (DD/BN, ceil(NN/BM), 3), 256 threads. Warp grid 4(m) x 2(n): 32x64/warp.
#define BM 128
#define BN 128
#define BK 32
#define LDA_H 40                       // halves per smem A row (pad 8)
#define LDB_H 136                      // halves per smem B row (pad 8)
#define A_BYTES (BM * LDA_H * 2)       // 10240
#define B_BYTES (BK * LDB_H * 2)       // 8704
#define STAGE_B (A_BYTES + B_BYTES)    // 18944
#define NT (DD / BK)                   // 16

__device__ __forceinline__ void cp16(uint32_t dst, const void* src, int sz) {
    asm volatile("cp.async.cg.shared.global [%0], [%1], 16, %2;"
                 :: "r"(dst), "l"(src), "r"(sz));
}

__global__ void __launch_bounds__(256, 2) k_gemm(
    const float* __restrict__ B2,
    const float* __restrict__ B3) {
    __shared__ __align__(128) char smem[2 * STAGE_B];
    const uint32_t sb = smem_to_u32(smem);
    const int tid = threadIdx.x;
    const int wid = tid >> 5;
    const int lane = tid & 31;
    const int warp_m = wid & 3;     // 4 m-stripes of 32 rows
    const int warp_n = wid >> 2;    // 2 n-stripes of 64 cols
    const int z = blockIdx.z;
    const int m0 = blockIdx.y * BM;
    const int n0 = blockIdx.x * BN;
    const __half* __restrict__ xh = g_xh;
    const __half* __restrict__ wh = g_wh + (size_t)z * DD * DD;

    // ---- stage loader: A 128x32 (4 chunks/row), B 32x128 (16 chunks/row)
    auto load_tile = [&](int buf, int kc) {
        const int k0 = kc * BK;
        const uint32_t base = sb + buf * STAGE_B;
        #pragma unroll
        for (int i = 0; i < 2; i++) {
            int idx = tid + i * 256;          // 0..511
            int row = idx >> 2;               // 0..127
            int ch = idx & 3;                 // 0..3 (8 halves each)
            int gr = m0 + row;
            int sz = (gr < NN) ? 16 : 0;
            const __half* src = xh + (size_t)gr * DD + k0 + ch * 8;
            cp16(base + row * (LDA_H * 2) + ch * 16, src, sz);
        }
        #pragma unroll
        for (int i = 0; i < 2; i++) {
            int idx = tid + i * 256;          // 0..511
            int row = idx >> 4;               // 0..31
            int ch = idx & 15;                // 0..15
            const __half* src = wh + (size_t)(k0 + row) * DD + n0 + ch * 8;
            cp16(base + A_BYTES + row * (LDB_H * 2) + ch * 16, src, 16);
        }
        asm volatile("cp.async.commit_group;");
    };

    float c[2][8][4];
    #pragma unroll
    for (int i = 0; i < 2; i++)
        #pragma unroll
        for (int j = 0; j < 8; j++)
            #pragma unroll
            for (int q = 0; q < 4; q++) c[i][j][q] = 0.f;

    load_tile(0, 0);
    load_tile(1, 1);

    for (int kc = 0; kc < NT; kc++) {
        const int buf = kc & 1;
        if (kc < NT - 2) {
            asm volatile("cp.async.wait_group 1;");
        } else {
            asm volatile("cp.async.wait_group 0;");
        }
        __syncthreads();

        const uint32_t abase = sb + buf * STAGE_B;
        const uint32_t bbase = abase + A_BYTES;

        #pragma unroll
        for (int kk = 0; kk < 2; kk++) {
            uint32_t a[2][4];
            #pragma unroll
            for (int i = 0; i < 2; i++) {
                int row = warp_m * 32 + i * 16 + (lane & 15);
                int col = kk * 16 + (lane >> 4) * 8;
                uint32_t addr = abase + row * (LDA_H * 2) + col * 2;
                asm volatile("ldmatrix.sync.aligned.m8n8.x4.shared.b16 {%0,%1,%2,%3}, [%4];"
                             : "=r"(a[i][0]), "=r"(a[i][1]), "=r"(a[i][2]), "=r"(a[i][3])
                             : "r"(addr));
            }
            uint32_t b[4][4];
            #pragma unroll
            for (int j2 = 0; j2 < 4; j2++) {
                int row = kk * 16 + (lane & 15);
                int col = warp_n * 64 + j2 * 16 + (lane >> 4) * 8;
                uint32_t addr = bbase + row * (LDB_H * 2) + col * 2;
                asm volatile("ldmatrix.sync.aligned.m8n8.x4.trans.shared.b16 {%0,%1,%2,%3}, [%4];"
                             : "=r"(b[j2][0]), "=r"(b[j2][1]), "=r"(b[j2][2]), "=r"(b[j2][3])
                             : "r"(addr));
            }
            #pragma unroll
            for (int i = 0; i < 2; i++) {
                #pragma unroll
                for (int j = 0; j < 8; j++) {
                    const uint32_t* bb = &b[j >> 1][(j & 1) * 2];
                    asm volatile(
                        "mma.sync.aligned.m16n8k16.row.col.f32.f16.f16.f32 "
                        "{%0,%1,%2,%3}, {%4,%5,%6,%7}, {%8,%9}, {%0,%1,%2,%3};"
                        : "+f"(c[i][j][0]), "+f"(c[i][j][1]), "+f"(c[i][j][2]), "+f"(c[i][j][3])
                        : "r"(a[i][0]), "r"(a[i][1]), "r"(a[i][2]), "r"(a[i][3]),
                          "r"(bb[0]), "r"(bb[1]));
                }
            }
        }
        __syncthreads();
        if (kc + 2 < NT) load_tile(buf, kc + 2);
    }

    // ---- epilogue (c layout: c0 (r, cc), c1 (r, cc+1), c2 (r+8, cc), c3 (r+8, cc+1))
    #pragma unroll
    for (int i = 0; i < 2; i++) {
        int r0 = m0 + warp_m * 32 + i * 16 + (lane >> 2);
        int r1 = r0 + 8;
        #pragma unroll
        for (int j = 0; j < 8; j++) {
            int cc = n0 + warp_n * 64 + j * 8 + (lane & 3) * 2;
            float v0 = c[i][j][0], v1 = c[i][j][1];
            float v2 = c[i][j][2], v3 = c[i][j][3];
            if (z == 0) {
                __half2 h0 = __float22half2_rn(make_float2(v0, v1));
                __half2 h1 = __float22half2_rn(make_float2(v2, v3));
                if (r0 < NN) *(__half2*)&g_suph[(size_t)r0 * DD + cc] = h0;
                if (r1 < NN) *(__half2*)&g_suph[(size_t)r1 * DD + cc] = h1;
            } else if (z == 1) {
                float bx = __ldg(&B2[cc]), by = __ldg(&B2[cc + 1]);
                if (r0 < NN) *(float2*)&g_trans[(size_t)r0 * DD + cc] = make_float2(v0 + bx, v1 + by);
                if (r1 < NN) *(float2*)&g_trans[(size_t)r1 * DD + cc] = make_float2(v2 + bx, v3 + by);
            } else {
                float bx = __ldg(&B3[cc]), by = __ldg(&B3[cc + 1]);
                if (r0 < NN) *(float2*)&g_gate[(size_t)r0 * DD + cc] =
                    make_float2(sigmoidf_(v0 + bx), sigmoidf_(v1 + by));
                if (r1 < NN) *(float2*)&g_gate[(size_t)r1 * DD + cc] =
                    make_float2(sigmoidf_(v2 + bx), sigmoidf_(v3 + by));
            }
        }
    }
}

// ---------------- warp-per-row SpMM (fp16 gathers) + fused epilogue -----------
__global__ void __launch_bounds__(256) k_spmm(const float* __restrict__ b1,
                                              float* __restrict__ out) {
    int gw = (blockIdx.x * blockDim.x + threadIdx.x) >> 5;
    int lane = threadIdx.x & 31;
    if (gw >= NN) return;
    int s = g_rowptr[gw];
    int e = g_rowptr[gw + 1];

    float acc[16];
    #pragma unroll
    for (int i = 0; i < 16; i++) acc[i] = 0.f;

    const uint4* sup = (const uint4*)g_suph;  // row = 64 uint4 (512 halves)

    for (int i = s; i < e; i++) {
        int2 ep = __ldg(&g_epack[i]);
        int c = ep.x;
        float v = __int_as_float(ep.y);
        const uint4* p = sup + (size_t)c * 64;
        uint4 q0 = __ldg(&p[lane]);
        uint4 q1 = __ldg(&p[lane + 32]);
        const __half2* h0 = (const __half2*)&q0;
        const __half2* h1 = (const __half2*)&q1;
        #pragma unroll
        for (int j = 0; j < 4; j++) {
            float2 f0 = __half22float2(h0[j]);
            float2 f1 = __half22float2(h1[j]);
            acc[j * 2 + 0] += v * f0.x;
            acc[j * 2 + 1] += v * f0.y;
            acc[8 + j * 2 + 0] += v * f1.x;
            acc[8 + j * 2 + 1] += v * f1.y;
        }
    }

    size_t ro = (size_t)gw * DD;
    #pragma unroll
    for (int h = 0; h < 2; h++) {
        int cb = h * 256 + lane * 8;
        #pragma unroll
        for (int g4 = 0; g4 < 2; g4++) {
            int col = cb + g4 * 4;
            float4 bb = *(const float4*)&b1[col];
            float4 t = *(const float4*)&g_trans[ro + col];
            float4 gg = *(const float4*)&g_gate[ro + col];
            const float* a = &acc[h * 8 + g4 * 4];
            float4 r;
            r.x = t.x + gg.x * (fmaxf(a[0] + bb.x, 0.f) - t.x);
            r.y = t.y + gg.y * (fmaxf(a[1] + bb.y, 0.f) - t.y);
            r.z = t.z + gg.z * (fmaxf(a[2] + bb.z, 0.f) - t.z);
            r.w = t.w + gg.w * (fmaxf(a[3] + bb.w, 0.f) - t.w);
            *(float4*)&out[ro + col] = r;
        }
    }
}

// ---------------- launch -------------------------------------------------------
extern "C" void kernel_launch(void* const* d_in, const int* in_sizes, int n_in,
                              void* d_out, int out_size) {
    const float* x   = (const float*)d_in[0];
    const float* w1  = (const float*)d_in[1];
    const float* w2  = (const float*)d_in[2];
    const float* w3  = (const float*)d_in[3];
    const float* b1  = (const float*)d_in[4];
    const float* b2  = (const float*)d_in[5];
    const float* b3  = (const float*)d_in[6];
    const int*   er  = (const int*)d_in[7];
    const int*   ec  = (const int*)d_in[8];
    const float* ev  = (const float*)d_in[9];
    float* out = (float*)d_out;

    // conversions
    k_xh<<<(NN * (DD / 4) + 255) / 256, 256>>>(x);
    k_wh<<<(3 * DD * DD / 4 + 255) / 256, 256>>>(w1, w2, w3);

    // CSR build
    k_init<<<(NN + 255) / 256, 256>>>();
    k_hist<<<(EE + 255) / 256, 256>>>(er);
    k_scan<<<1, 1024>>>();
    k_scatter<<<(EE + 255) / 256, 256>>>(er, ec, ev);

    // fp16 tensor-core triple projection
    dim3 ggrid(DD / BN, (NN + BM - 1) / BM, 3);
    k_gemm<<<ggrid, 256>>>(b2, b3);

    // SpMM + fused relu + gated combine
    int warps_per_block = 8;
    int blocks = (NN + warps_per_block - 1) / warps_per_block;
    k_spmm<<<blocks, warps_per_block * 32>>>(b1, out);
}

// round 4
// speedup vs baseline: 2.8444x; 1.0226x over previous
#include <cuda_runtime.h>
#include <cuda_fp16.h>
#include <cstdint>
#include <math.h>

#define NN 100000
#define DD 512
#define EE 3200000

// ---------------- scratch (__device__ globals) --------------------------------
__device__ __half g_suph[(size_t)NN * DD];   // support in fp16 (gathered a lot)
__device__ float  g_trans[(size_t)NN * DD];
__device__ float  g_gate[(size_t)NN * DD];
__device__ __half g_xh[(size_t)NN * DD];     // x in fp16
__device__ __half g_wh[3 * DD * DD];         // weights in fp16, [z][k][n]
__device__ int    g_deg[NN];
__device__ int    g_cursor[NN];
__device__ int    g_rowptr[NN + 1];
__device__ int2   g_epack[EE];               // packed (col, val bits)

__device__ __forceinline__ uint32_t smem_to_u32(const void* smem_ptr) {
    uint32_t addr;
    asm("{ .reg .u64 tmp; cvta.to.shared.u64 tmp, %1; cvt.u32.u64 %0, tmp; }"
        : "=r"(addr) : "l"(smem_ptr));
    return addr;
}

__device__ __forceinline__ float sigmoidf_(float x) {
    return 1.0f / (1.0f + __expf(-x));
}

// ---------------- CSR build ---------------------------------------------------
__global__ void k_init() {
    int i = blockIdx.x * blockDim.x + threadIdx.x;
    if (i < NN) { g_deg[i] = 0; g_cursor[i] = 0; }
}

__global__ void k_hist(const int* __restrict__ erow) {
    int e = blockIdx.x * blockDim.x + threadIdx.x;
    if (e < EE) atomicAdd(&g_deg[erow[e]], 1);
}

__global__ void k_scan() {
    __shared__ int s[1024];
    const int CH = (NN + 1023) / 1024;
    int t = threadIdx.x;
    int start = t * CH;
    int end = start + CH; if (end > NN) end = NN;
    int sum = 0;
    for (int i = start; i < end; i++) sum += g_deg[i];
    s[t] = sum;
    __syncthreads();
    for (int off = 1; off < 1024; off <<= 1) {
        int v = (t >= off) ? s[t - off] : 0;
        __syncthreads();
        s[t] += v;
        __syncthreads();
    }
    int excl = s[t] - sum;
    for (int i = start; i < end; i++) {
        g_rowptr[i] = excl;
        excl += g_deg[i];
    }
    if (t == 1023) g_rowptr[NN] = s[1023];
}

__global__ void k_scatter(const int* __restrict__ erow,
                          const int* __restrict__ ecol,
                          const float* __restrict__ eval) {
    int e = blockIdx.x * blockDim.x + threadIdx.x;
    if (e < EE) {
        int r = erow[e];
        int pos = g_rowptr[r] + atomicAdd(&g_cursor[r], 1);
        g_epack[pos] = make_int2(ecol[e], __float_as_int(eval[e]));
    }
}

// ---------------- fp32 -> fp16 conversions ------------------------------------
__global__ void k_xh(const float* __restrict__ x) {
    int idx = blockIdx.x * blockDim.x + threadIdx.x;   // over N*DD/4
    if (idx < NN * (DD / 4)) {
        float4 v = *(const float4*)&x[(size_t)idx * 4];
        __half2 h[2];
        h[0] = __float22half2_rn(make_float2(v.x, v.y));
        h[1] = __float22half2_rn(make_float2(v.z, v.w));
        *(uint2*)&g_xh[(size_t)idx * 4] = *(uint2*)h;
    }
}

__global__ void k_wh(const float* __restrict__ w1,
                     const float* __restrict__ w2,
                     const float* __restrict__ w3) {
    int idx = blockIdx.x * blockDim.x + threadIdx.x;   // over 3*DD*DD/4
    if (idx < 3 * DD * DD / 4) {
        int z = idx / (DD * DD / 4);
        int off = idx - z * (DD * DD / 4);
        const float* w = (z == 0) ? w1 : ((z == 1) ? w2 : w3);
        float4 v = *(const float4*)&w[(size_t)off * 4];
        __half2 h[2];
        h[0] = __float22half2_rn(make_float2(v.x, v.y));
        h[1] = __float22half2_rn(make_float2(v.z, v.w));
        *(uint2*)&g_wh[(size_t)z * DD * DD + (size_t)off * 4] = *(uint2*)h;
    }
}

// ---------------- fp16 mma.sync GEMM ------------------------------------------
// grid (DD/BN, ceil(NN/BM)), 256 threads. Warp grid 4(m) x 2(n): 32x64/warp.
#define BM 128
#define BN 128
#define BK 32
#define LDA_H 40                       // halves per smem A row (pad 8)
#define LDB_H 136                      // halves per smem B row (pad 8)
#define A_BYTES (BM * LDA_H * 2)       // 10240
#define B_BYTES (BK * LDB_H * 2)       // 8704
#define STAGE_B (A_BYTES + B_BYTES)    // 18944
#define NT (DD / BK)                   // 16

__device__ __forceinline__ void cp16(uint32_t dst, const void* src, int sz) {
    asm volatile("cp.async.cg.shared.global [%0], [%1], 16, %2;"
                 :: "r"(dst), "l"(src), "r"(sz));
}

__global__ void __launch_bounds__(256, 2) k_gemm(
    int z,
    const float* __restrict__ B2,
    const float* __restrict__ B3) {
    __shared__ __align__(128) char smem[2 * STAGE_B];
    const uint32_t sb = smem_to_u32(smem);
    const int tid = threadIdx.x;
    const int wid = tid >> 5;
    const int lane = tid & 31;
    const int warp_m = wid & 3;     // 4 m-stripes of 32 rows
    const int warp_n = wid >> 2;    // 2 n-stripes of 64 cols
    const int m0 = blockIdx.y * BM;
    const int n0 = blockIdx.x * BN;
    const __half* __restrict__ xh = g_xh;
    const __half* __restrict__ wh = g_wh + (size_t)z * DD * DD;

    auto load_tile = [&](int buf, int kc) {
        const int k0 = kc * BK;
        const uint32_t base = sb + buf * STAGE_B;
        #pragma unroll
        for (int i = 0; i < 2; i++) {
            int idx = tid + i * 256;          // 0..511
            int row = idx >> 2;               // 0..127
            int ch = idx & 3;                 // 0..3 (8 halves each)
            int gr = m0 + row;
            int sz = (gr < NN) ? 16 : 0;
            const __half* src = xh + (size_t)gr * DD + k0 + ch * 8;
            cp16(base + row * (LDA_H * 2) + ch * 16, src, sz);
        }
        #pragma unroll
        for (int i = 0; i < 2; i++) {
            int idx = tid + i * 256;          // 0..511
            int row = idx >> 4;               // 0..31
            int ch = idx & 15;                // 0..15
            const __half* src = wh + (size_t)(k0 + row) * DD + n0 + ch * 8;
            cp16(base + A_BYTES + row * (LDB_H * 2) + ch * 16, src, 16);
        }
        asm volatile("cp.async.commit_group;");
    };

    float c[2][8][4];
    #pragma unroll
    for (int i = 0; i < 2; i++)
        #pragma unroll
        for (int j = 0; j < 8; j++)
            #pragma unroll
            for (int q = 0; q < 4; q++) c[i][j][q] = 0.f;

    load_tile(0, 0);
    load_tile(1, 1);

    for (int kc = 0; kc < NT; kc++) {
        const int buf = kc & 1;
        if (kc < NT - 2) {
            asm volatile("cp.async.wait_group 1;");
        } else {
            asm volatile("cp.async.wait_group 0;");
        }
        __syncthreads();

        const uint32_t abase = sb + buf * STAGE_B;
        const uint32_t bbase = abase + A_BYTES;

        #pragma unroll
        for (int kk = 0; kk < 2; kk++) {
            uint32_t a[2][4];
            #pragma unroll
            for (int i = 0; i < 2; i++) {
                int row = warp_m * 32 + i * 16 + (lane & 15);
                int col = kk * 16 + (lane >> 4) * 8;
                uint32_t addr = abase + row * (LDA_H * 2) + col * 2;
                asm volatile("ldmatrix.sync.aligned.m8n8.x4.shared.b16 {%0,%1,%2,%3}, [%4];"
                             : "=r"(a[i][0]), "=r"(a[i][1]), "=r"(a[i][2]), "=r"(a[i][3])
                             : "r"(addr));
            }
            uint32_t b[4][4];
            #pragma unroll
            for (int j2 = 0; j2 < 4; j2++) {
                int row = kk * 16 + (lane & 15);
                int col = warp_n * 64 + j2 * 16 + (lane >> 4) * 8;
                uint32_t addr = bbase + row * (LDB_H * 2) + col * 2;
                asm volatile("ldmatrix.sync.aligned.m8n8.x4.trans.shared.b16 {%0,%1,%2,%3}, [%4];"
                             : "=r"(b[j2][0]), "=r"(b[j2][1]), "=r"(b[j2][2]), "=r"(b[j2][3])
                             : "r"(addr));
            }
            #pragma unroll
            for (int i = 0; i < 2; i++) {
                #pragma unroll
                for (int j = 0; j < 8; j++) {
                    const uint32_t* bb = &b[j >> 1][(j & 1) * 2];
                    asm volatile(
                        "mma.sync.aligned.m16n8k16.row.col.f32.f16.f16.f32 "
                        "{%0,%1,%2,%3}, {%4,%5,%6,%7}, {%8,%9}, {%0,%1,%2,%3};"
                        : "+f"(c[i][j][0]), "+f"(c[i][j][1]), "+f"(c[i][j][2]), "+f"(c[i][j][3])
                        : "r"(a[i][0]), "r"(a[i][1]), "r"(a[i][2]), "r"(a[i][3]),
                          "r"(bb[0]), "r"(bb[1]));
                }
            }
        }
        __syncthreads();
        if (kc + 2 < NT) load_tile(buf, kc + 2);
    }

    // ---- epilogue
    #pragma unroll
    for (int i = 0; i < 2; i++) {
        int r0 = m0 + warp_m * 32 + i * 16 + (lane >> 2);
        int r1 = r0 + 8;
        #pragma unroll
        for (int j = 0; j < 8; j++) {
            int cc = n0 + warp_n * 64 + j * 8 + (lane & 3) * 2;
            float v0 = c[i][j][0], v1 = c[i][j][1];
            float v2 = c[i][j][2], v3 = c[i][j][3];
            if (z == 0) {
                __half2 h0 = __float22half2_rn(make_float2(v0, v1));
                __half2 h1 = __float22half2_rn(make_float2(v2, v3));
                if (r0 < NN) *(__half2*)&g_suph[(size_t)r0 * DD + cc] = h0;
                if (r1 < NN) *(__half2*)&g_suph[(size_t)r1 * DD + cc] = h1;
            } else if (z == 1) {
                float bx = __ldg(&B2[cc]), by = __ldg(&B2[cc + 1]);
                if (r0 < NN) *(float2*)&g_trans[(size_t)r0 * DD + cc] = make_float2(v0 + bx, v1 + by);
                if (r1 < NN) *(float2*)&g_trans[(size_t)r1 * DD + cc] = make_float2(v2 + bx, v3 + by);
            } else {
                float bx = __ldg(&B3[cc]), by = __ldg(&B3[cc + 1]);
                if (r0 < NN) *(float2*)&g_gate[(size_t)r0 * DD + cc] =
                    make_float2(sigmoidf_(v0 + bx), sigmoidf_(v1 + by));
                if (r1 < NN) *(float2*)&g_gate[(size_t)r1 * DD + cc] =
                    make_float2(sigmoidf_(v2 + bx), sigmoidf_(v3 + by));
            }
        }
    }
}

// ---------------- warp-per-row SpMM (fp16 gathers), writes relu(agg+b1) -------
__global__ void __launch_bounds__(256) k_spmm(const float* __restrict__ b1,
                                              float* __restrict__ out) {
    int gw = (blockIdx.x * blockDim.x + threadIdx.x) >> 5;
    int lane = threadIdx.x & 31;
    if (gw >= NN) return;
    int s = g_rowptr[gw];
    int e = g_rowptr[gw + 1];

    float acc[16];
    #pragma unroll
    for (int i = 0; i < 16; i++) acc[i] = 0.f;

    const uint4* sup = (const uint4*)g_suph;  // row = 64 uint4 (512 halves)

    int i = s;
    for (; i + 2 <= e; i += 2) {
        int2 ep0 = __ldg(&g_epack[i]);
        int2 ep1 = __ldg(&g_epack[i + 1]);
        float v0 = __int_as_float(ep0.y);
        float v1 = __int_as_float(ep1.y);
        const uint4* p0 = sup + (size_t)ep0.x * 64;
        const uint4* p1 = sup + (size_t)ep1.x * 64;
        uint4 qa0 = __ldg(&p0[lane]);
        uint4 qa1 = __ldg(&p0[lane + 32]);
        uint4 qb0 = __ldg(&p1[lane]);
        uint4 qb1 = __ldg(&p1[lane + 32]);
        const __half2* ha0 = (const __half2*)&qa0;
        const __half2* ha1 = (const __half2*)&qa1;
        const __half2* hb0 = (const __half2*)&qb0;
        const __half2* hb1 = (const __half2*)&qb1;
        #pragma unroll
        for (int j = 0; j < 4; j++) {
            float2 fa0 = __half22float2(ha0[j]);
            float2 fa1 = __half22float2(ha1[j]);
            float2 fb0 = __half22float2(hb0[j]);
            float2 fb1 = __half22float2(hb1[j]);
            acc[j * 2 + 0] += v0 * fa0.x + v1 * fb0.x;
            acc[j * 2 + 1] += v0 * fa0.y + v1 * fb0.y;
            acc[8 + j * 2 + 0] += v0 * fa1.x + v1 * fb1.x;
            acc[8 + j * 2 + 1] += v0 * fa1.y + v1 * fb1.y;
        }
    }
    for (; i < e; i++) {
        int2 ep = __ldg(&g_epack[i]);
        float v = __int_as_float(ep.y);
        const uint4* p = sup + (size_t)ep.x * 64;
        uint4 q0 = __ldg(&p[lane]);
        uint4 q1 = __ldg(&p[lane + 32]);
        const __half2* h0 = (const __half2*)&q0;
        const __half2* h1 = (const __half2*)&q1;
        #pragma unroll
        for (int j = 0; j < 4; j++) {
            float2 f0 = __half22float2(h0[j]);
            float2 f1 = __half22float2(h1[j]);
            acc[j * 2 + 0] += v * f0.x;
            acc[j * 2 + 1] += v * f0.y;
            acc[8 + j * 2 + 0] += v * f1.x;
            acc[8 + j * 2 + 1] += v * f1.y;
        }
    }

    // write relu(agg + b1) to out (combine comes later)
    size_t ro = (size_t)gw * DD;
    #pragma unroll
    for (int h = 0; h < 2; h++) {
        int cb = h * 256 + lane * 8;
        #pragma unroll
        for (int g4 = 0; g4 < 2; g4++) {
            int col = cb + g4 * 4;
            float4 bb = *(const float4*)&b1[col];
            const float* a = &acc[h * 8 + g4 * 4];
            float4 r;
            r.x = fmaxf(a[0] + bb.x, 0.f);
            r.y = fmaxf(a[1] + bb.y, 0.f);
            r.z = fmaxf(a[2] + bb.z, 0.f);
            r.w = fmaxf(a[3] + bb.w, 0.f);
            *(float4*)&out[ro + col] = r;
        }
    }
}

// ---------------- final gated combine -----------------------------------------
__global__ void __launch_bounds__(256) k_combine(float* __restrict__ out) {
    int idx = blockIdx.x * blockDim.x + threadIdx.x;   // over N*DD/4
    if (idx < NN * (DD / 4)) {
        float4 t = *(const float4*)&g_trans[(size_t)idx * 4];
        float4 g = *(const float4*)&g_gate[(size_t)idx * 4];
        float4 r = *(const float4*)&out[(size_t)idx * 4];
        float4 o;
        o.x = t.x + g.x * (r.x - t.x);
        o.y = t.y + g.y * (r.y - t.y);
        o.z = t.z + g.z * (r.z - t.z);
        o.w = t.w + g.w * (r.w - t.w);
        *(float4*)&out[(size_t)idx * 4] = o;
    }
}

// ---------------- launch -------------------------------------------------------
extern "C" void kernel_launch(void* const* d_in, const int* in_sizes, int n_in,
                              void* d_out, int out_size) {
    const float* x   = (const float*)d_in[0];
    const float* w1  = (const float*)d_in[1];
    const float* w2  = (const float*)d_in[2];
    const float* w3  = (const float*)d_in[3];
    const float* b1  = (const float*)d_in[4];
    const float* b2  = (const float*)d_in[5];
    const float* b3  = (const float*)d_in[6];
    const int*   er  = (const int*)d_in[7];
    const int*   ec  = (const int*)d_in[8];
    const float* ev  = (const float*)d_in[9];
    float* out = (float*)d_out;

    static cudaStream_t sA = nullptr, sB = nullptr;
    static cudaEvent_t evRoot = nullptr, evSup = nullptr, evGemm = nullptr, evAgg = nullptr;
    if (!sA) {
        cudaStreamCreateWithFlags(&sA, cudaStreamNonBlocking);
        cudaStreamCreateWithFlags(&sB, cudaStreamNonBlocking);
        cudaEventCreateWithFlags(&evRoot, cudaEventDisableTiming);
        cudaEventCreateWithFlags(&evSup, cudaEventDisableTiming);
        cudaEventCreateWithFlags(&evGemm, cudaEventDisableTiming);
        cudaEventCreateWithFlags(&evAgg, cudaEventDisableTiming);
    }

    // fork from the capture-origin stream
    cudaEventRecord(evRoot, 0);
    cudaStreamWaitEvent(sA, evRoot, 0);
    cudaStreamWaitEvent(sB, evRoot, 0);

    dim3 ggrid(DD / BN, (NN + BM - 1) / BM);

    // --- stream A: conversions + triple GEMM (submission order puts gemm z0 at idx 3)
    k_xh<<<(NN * (DD / 4) + 255) / 256, 256, 0, sA>>>(x);
    k_wh<<<(3 * DD * DD / 4 + 255) / 256, 256, 0, sA>>>(w1, w2, w3);
    k_init<<<(NN + 255) / 256, 256, 0, sB>>>();
    k_gemm<<<ggrid, 256, 0, sA>>>(0, b2, b3);       // support (fp16)
    cudaEventRecord(evSup, sA);
    // --- stream B: CSR build
    k_hist<<<(EE + 255) / 256, 256, 0, sB>>>(er);
    k_scan<<<1, 1024, 0, sB>>>();
    k_scatter<<<(EE + 255) / 256, 256, 0, sB>>>(er, ec, ev);
    // --- stream A continues with trans/gate GEMMs (overlap with SpMM below)
    k_gemm<<<ggrid, 256, 0, sA>>>(1, b2, b3);       // trans
    k_gemm<<<ggrid, 256, 0, sA>>>(2, b2, b3);       // gate
    cudaEventRecord(evGemm, sA);
    // --- stream B: SpMM (needs support + CSR)
    cudaStreamWaitEvent(sB, evSup, 0);
    {
        int warps_per_block = 8;
        int blocks = (NN + warps_per_block - 1) / warps_per_block;
        k_spmm<<<blocks, warps_per_block * 32, 0, sB>>>(b1, out);
    }
    cudaEventRecord(evAgg, sB);

    // --- join on origin stream, final combine
    cudaStreamWaitEvent(0, evGemm, 0);
    cudaStreamWaitEvent(0, evAgg, 0);
    k_combine<<<(NN * (DD / 4) + 255) / 256, 256>>>(out);
}

// round 5
// speedup vs baseline: 2.9914x; 1.0517x over previous
#include <cuda_runtime.h>
#include <cuda_fp16.h>
#include <cstdint>
#include <math.h>

#define NN 100000
#define DD 512
#define EE 3200000

// ---------------- scratch (__device__ globals) --------------------------------
__device__ __half g_suph[(size_t)NN * DD];   // support in fp16 (gathered a lot)
__device__ float  g_trans[(size_t)NN * DD];
__device__ float  g_gate[(size_t)NN * DD];
__device__ __half g_xh[(size_t)NN * DD];     // x in fp16
__device__ __half g_wh[3 * DD * DD];         // weights in fp16, [z][k][n]
__device__ int    g_deg[NN];
__device__ int    g_cursor[NN];
__device__ int    g_rowptr[NN + 1];
__device__ int2   g_epack[EE];               // packed (col, val bits)

__device__ __forceinline__ uint32_t smem_to_u32(const void* smem_ptr) {
    uint32_t addr;
    asm("{ .reg .u64 tmp; cvta.to.shared.u64 tmp, %1; cvt.u32.u64 %0, tmp; }"
        : "=r"(addr) : "l"(smem_ptr));
    return addr;
}

__device__ __forceinline__ float sigmoidf_(float x) {
    return 1.0f / (1.0f + __expf(-x));
}

// ---------------- CSR build ---------------------------------------------------
__global__ void k_init() {
    int i = blockIdx.x * blockDim.x + threadIdx.x;
    if (i < NN) { g_deg[i] = 0; g_cursor[i] = 0; }
}

__global__ void k_hist(const int* __restrict__ erow) {
    int e = blockIdx.x * blockDim.x + threadIdx.x;
    if (e < EE) atomicAdd(&g_deg[erow[e]], 1);
}

__global__ void k_scan() {
    __shared__ int s[1024];
    const int CH = (NN + 1023) / 1024;
    int t = threadIdx.x;
    int start = t * CH;
    int end = start + CH; if (end > NN) end = NN;
    int sum = 0;
    for (int i = start; i < end; i++) sum += g_deg[i];
    s[t] = sum;
    __syncthreads();
    for (int off = 1; off < 1024; off <<= 1) {
        int v = (t >= off) ? s[t - off] : 0;
        __syncthreads();
        s[t] += v;
        __syncthreads();
    }
    int excl = s[t] - sum;
    for (int i = start; i < end; i++) {
        g_rowptr[i] = excl;
        excl += g_deg[i];
    }
    if (t == 1023) g_rowptr[NN] = s[1023];
}

__global__ void k_scatter(const int* __restrict__ erow,
                          const int* __restrict__ ecol,
                          const float* __restrict__ eval) {
    int e = blockIdx.x * blockDim.x + threadIdx.x;
    if (e < EE) {
        int r = erow[e];
        int pos = g_rowptr[r] + atomicAdd(&g_cursor[r], 1);
        g_epack[pos] = make_int2(ecol[e], __float_as_int(eval[e]));
    }
}

// ---------------- fp32 -> fp16 conversions ------------------------------------
__global__ void k_xh(const float* __restrict__ x) {
    int idx = blockIdx.x * blockDim.x + threadIdx.x;   // over N*DD/4
    if (idx < NN * (DD / 4)) {
        float4 v = *(const float4*)&x[(size_t)idx * 4];
        __half2 h[2];
        h[0] = __float22half2_rn(make_float2(v.x, v.y));
        h[1] = __float22half2_rn(make_float2(v.z, v.w));
        *(uint2*)&g_xh[(size_t)idx * 4] = *(uint2*)h;
    }
}

__global__ void k_wh(const float* __restrict__ w1,
                     const float* __restrict__ w2,
                     const float* __restrict__ w3) {
    int idx = blockIdx.x * blockDim.x + threadIdx.x;   // over 3*DD*DD/4
    if (idx < 3 * DD * DD / 4) {
        int z = idx / (DD * DD / 4);
        int off = idx - z * (DD * DD / 4);
        const float* w = (z == 0) ? w1 : ((z == 1) ? w2 : w3);
        float4 v = *(const float4*)&w[(size_t)off * 4];
        __half2 h[2];
        h[0] = __float22half2_rn(make_float2(v.x, v.y));
        h[1] = __float22half2_rn(make_float2(v.z, v.w));
        *(uint2*)&g_wh[(size_t)z * DD * DD + (size_t)off * 4] = *(uint2*)h;
    }
}

// ---------------- fp16 mma.sync GEMM, 4-stage cp.async pipeline ----------------
// grid (DD/BN, ceil(NN/BM)), 256 threads. Warp grid 4(m) x 2(n): 32x64/warp.
#define BM 128
#define BN 128
#define BK 32
#define LDA_H 40                       // halves per smem A row (pad 8)
#define LDB_H 136                      // halves per smem B row (pad 8)
#define A_BYTES (BM * LDA_H * 2)       // 10240
#define B_BYTES (BK * LDB_H * 2)       // 8704
#define STAGE_B (A_BYTES + B_BYTES)    // 18944
#define NSTAGE 4
#define SMEM_GEMM (NSTAGE * STAGE_B)   // 75776
#define NT (DD / BK)                   // 16

__device__ __forceinline__ void cp16(uint32_t dst, const void* src, int sz) {
    asm volatile("cp.async.cg.shared.global [%0], [%1], 16, %2;"
                 :: "r"(dst), "l"(src), "r"(sz));
}

__global__ void __launch_bounds__(256, 2) k_gemm(
    int z,
    const float* __restrict__ B2,
    const float* __restrict__ B3) {
    extern __shared__ __align__(128) char smem[];
    const uint32_t sb = smem_to_u32(smem);
    const int tid = threadIdx.x;
    const int wid = tid >> 5;
    const int lane = tid & 31;
    const int warp_m = wid & 3;     // 4 m-stripes of 32 rows
    const int warp_n = wid >> 2;    // 2 n-stripes of 64 cols
    const int m0 = blockIdx.y * BM;
    const int n0 = blockIdx.x * BN;
    const __half* __restrict__ xh = g_xh;
    const __half* __restrict__ wh = g_wh + (size_t)z * DD * DD;

    auto load_tile = [&](int buf, int kc) {
        const int k0 = kc * BK;
        const uint32_t base = sb + buf * STAGE_B;
        #pragma unroll
        for (int i = 0; i < 2; i++) {
            int idx = tid + i * 256;          // 0..511
            int row = idx >> 2;               // 0..127
            int ch = idx & 3;                 // 0..3 (8 halves each)
            int gr = m0 + row;
            int sz = (gr < NN) ? 16 : 0;
            const __half* src = xh + (size_t)gr * DD + k0 + ch * 8;
            cp16(base + row * (LDA_H * 2) + ch * 16, src, sz);
        }
        #pragma unroll
        for (int i = 0; i < 2; i++) {
            int idx = tid + i * 256;          // 0..511
            int row = idx >> 4;               // 0..31
            int ch = idx & 15;                // 0..15
            const __half* src = wh + (size_t)(k0 + row) * DD + n0 + ch * 8;
            cp16(base + A_BYTES + row * (LDB_H * 2) + ch * 16, src, 16);
        }
        asm volatile("cp.async.commit_group;");
    };

    float c[2][8][4];
    #pragma unroll
    for (int i = 0; i < 2; i++)
        #pragma unroll
        for (int j = 0; j < 8; j++)
            #pragma unroll
            for (int q = 0; q < 4; q++) c[i][j][q] = 0.f;

    load_tile(0, 0);
    load_tile(1, 1);
    load_tile(2, 2);

    for (int kc = 0; kc < NT; kc++) {
        const int buf = kc & (NSTAGE - 1);
        // guarantee tile kc is resident: keep at most (#tiles newer than kc) pending
        if (kc < NT - 2)       asm volatile("cp.async.wait_group 2;");
        else if (kc == NT - 2) asm volatile("cp.async.wait_group 1;");
        else                   asm volatile("cp.async.wait_group 0;");
        __syncthreads();   // also protects buf (kc+3)&3 == (kc-1)&3 reads from last iter

        // issue next tile's loads BEFORE compute so they overlap the MMAs
        if (kc + 3 < NT) load_tile((kc + 3) & (NSTAGE - 1), kc + 3);

        const uint32_t abase = sb + buf * STAGE_B;
        const uint32_t bbase = abase + A_BYTES;

        #pragma unroll
        for (int kk = 0; kk < 2; kk++) {
            uint32_t a[2][4];
            #pragma unroll
            for (int i = 0; i < 2; i++) {
                int row = warp_m * 32 + i * 16 + (lane & 15);
                int col = kk * 16 + (lane >> 4) * 8;
                uint32_t addr = abase + row * (LDA_H * 2) + col * 2;
                asm volatile("ldmatrix.sync.aligned.m8n8.x4.shared.b16 {%0,%1,%2,%3}, [%4];"
                             : "=r"(a[i][0]), "=r"(a[i][1]), "=r"(a[i][2]), "=r"(a[i][3])
                             : "r"(addr));
            }
            uint32_t b[4][4];
            #pragma unroll
            for (int j2 = 0; j2 < 4; j2++) {
                int row = kk * 16 + (lane & 15);
                int col = warp_n * 64 + j2 * 16 + (lane >> 4) * 8;
                uint32_t addr = bbase + row * (LDB_H * 2) + col * 2;
                asm volatile("ldmatrix.sync.aligned.m8n8.x4.trans.shared.b16 {%0,%1,%2,%3}, [%4];"
                             : "=r"(b[j2][0]), "=r"(b[j2][1]), "=r"(b[j2][2]), "=r"(b[j2][3])
                             : "r"(addr));
            }
            #pragma unroll
            for (int i = 0; i < 2; i++) {
                #pragma unroll
                for (int j = 0; j < 8; j++) {
                    const uint32_t* bb = &b[j >> 1][(j & 1) * 2];
                    asm volatile(
                        "mma.sync.aligned.m16n8k16.row.col.f32.f16.f16.f32 "
                        "{%0,%1,%2,%3}, {%4,%5,%6,%7}, {%8,%9}, {%0,%1,%2,%3};"
                        : "+f"(c[i][j][0]), "+f"(c[i][j][1]), "+f"(c[i][j][2]), "+f"(c[i][j][3])
                        : "r"(a[i][0]), "r"(a[i][1]), "r"(a[i][2]), "r"(a[i][3]),
                          "r"(bb[0]), "r"(bb[1]));
                }
            }
        }
    }

    // ---- epilogue
    #pragma unroll
    for (int i = 0; i < 2; i++) {
        int r0 = m0 + warp_m * 32 + i * 16 + (lane >> 2);
        int r1 = r0 + 8;
        #pragma unroll
        for (int j = 0; j < 8; j++) {
            int cc = n0 + warp_n * 64 + j * 8 + (lane & 3) * 2;
            float v0 = c[i][j][0], v1 = c[i][j][1];
            float v2 = c[i][j][2], v3 = c[i][j][3];
            if (z == 0) {
                __half2 h0 = __float22half2_rn(make_float2(v0, v1));
                __half2 h1 = __float22half2_rn(make_float2(v2, v3));
                if (r0 < NN) *(__half2*)&g_suph[(size_t)r0 * DD + cc] = h0;
                if (r1 < NN) *(__half2*)&g_suph[(size_t)r1 * DD + cc] = h1;
            } else if (z == 1) {
                float bx = __ldg(&B2[cc]), by = __ldg(&B2[cc + 1]);
                if (r0 < NN) *(float2*)&g_trans[(size_t)r0 * DD + cc] = make_float2(v0 + bx, v1 + by);
                if (r1 < NN) *(float2*)&g_trans[(size_t)r1 * DD + cc] = make_float2(v2 + bx, v3 + by);
            } else {
                float bx = __ldg(&B3[cc]), by = __ldg(&B3[cc + 1]);
                if (r0 < NN) *(float2*)&g_gate[(size_t)r0 * DD + cc] =
                    make_float2(sigmoidf_(v0 + bx), sigmoidf_(v1 + by));
                if (r1 < NN) *(float2*)&g_gate[(size_t)r1 * DD + cc] =
                    make_float2(sigmoidf_(v2 + bx), sigmoidf_(v3 + by));
            }
        }
    }
}

// ---------------- warp-per-row SpMM (fp16 gathers), writes relu(agg+b1) -------
// unroll x4: 8 independent 16B gathers in flight per warp
__global__ void __launch_bounds__(256) k_spmm(const float* __restrict__ b1,
                                              float* __restrict__ out) {
    int gw = (blockIdx.x * blockDim.x + threadIdx.x) >> 5;
    int lane = threadIdx.x & 31;
    if (gw >= NN) return;
    int s = g_rowptr[gw];
    int e = g_rowptr[gw + 1];

    float acc[16];
    #pragma unroll
    for (int i = 0; i < 16; i++) acc[i] = 0.f;

    const uint4* sup = (const uint4*)g_suph;  // row = 64 uint4 (512 halves)

    int i = s;
    for (; i + 4 <= e; i += 4) {
        int2 ep[4];
        #pragma unroll
        for (int u = 0; u < 4; u++) ep[u] = __ldg(&g_epack[i + u]);
        uint4 q0[4], q1[4];
        #pragma unroll
        for (int u = 0; u < 4; u++) {
            const uint4* p = sup + (size_t)ep[u].x * 64;
            q0[u] = __ldg(&p[lane]);
            q1[u] = __ldg(&p[lane + 32]);
        }
        #pragma unroll
        for (int u = 0; u < 4; u++) {
            float v = __int_as_float(ep[u].y);
            const __half2* h0 = (const __half2*)&q0[u];
            const __half2* h1 = (const __half2*)&q1[u];
            #pragma unroll
            for (int j = 0; j < 4; j++) {
                float2 f0 = __half22float2(h0[j]);
                float2 f1 = __half22float2(h1[j]);
                acc[j * 2 + 0] += v * f0.x;
                acc[j * 2 + 1] += v * f0.y;
                acc[8 + j * 2 + 0] += v * f1.x;
                acc[8 + j * 2 + 1] += v * f1.y;
            }
        }
    }
    for (; i < e; i++) {
        int2 ep = __ldg(&g_epack[i]);
        float v = __int_as_float(ep.y);
        const uint4* p = sup + (size_t)ep.x * 64;
        uint4 q0 = __ldg(&p[lane]);
        uint4 q1 = __ldg(&p[lane + 32]);
        const __half2* h0 = (const __half2*)&q0;
        const __half2* h1 = (const __half2*)&q1;
        #pragma unroll
        for (int j = 0; j < 4; j++) {
            float2 f0 = __half22float2(h0[j]);
            float2 f1 = __half22float2(h1[j]);
            acc[j * 2 + 0] += v * f0.x;
            acc[j * 2 + 1] += v * f0.y;
            acc[8 + j * 2 + 0] += v * f1.x;
            acc[8 + j * 2 + 1] += v * f1.y;
        }
    }

    // write relu(agg + b1) to out (combine comes later)
    size_t ro = (size_t)gw * DD;
    #pragma unroll
    for (int h = 0; h < 2; h++) {
        int cb = h * 256 + lane * 8;
        #pragma unroll
        for (int g4 = 0; g4 < 2; g4++) {
            int col = cb + g4 * 4;
            float4 bb = *(const float4*)&b1[col];
            const float* a = &acc[h * 8 + g4 * 4];
            float4 r;
            r.x = fmaxf(a[0] + bb.x, 0.f);
            r.y = fmaxf(a[1] + bb.y, 0.f);
            r.z = fmaxf(a[2] + bb.z, 0.f);
            r.w = fmaxf(a[3] + bb.w, 0.f);
            *(float4*)&out[ro + col] = r;
        }
    }
}

// ---------------- final gated combine -----------------------------------------
__global__ void __launch_bounds__(256) k_combine(float* __restrict__ out) {
    int idx = blockIdx.x * blockDim.x + threadIdx.x;   // over N*DD/4
    if (idx < NN * (DD / 4)) {
        float4 t = *(const float4*)&g_trans[(size_t)idx * 4];
        float4 g = *(const float4*)&g_gate[(size_t)idx * 4];
        float4 r = *(const float4*)&out[(size_t)idx * 4];
        float4 o;
        o.x = t.x + g.x * (r.x - t.x);
        o.y = t.y + g.y * (r.y - t.y);
        o.z = t.z + g.z * (r.z - t.z);
        o.w = t.w + g.w * (r.w - t.w);
        *(float4*)&out[(size_t)idx * 4] = o;
    }
}

// ---------------- launch -------------------------------------------------------
extern "C" void kernel_launch(void* const* d_in, const int* in_sizes, int n_in,
                              void* d_out, int out_size) {
    const float* x   = (const float*)d_in[0];
    const float* w1  = (const float*)d_in[1];
    const float* w2  = (const float*)d_in[2];
    const float* w3  = (const float*)d_in[3];
    const float* b1  = (const float*)d_in[4];
    const float* b2  = (const float*)d_in[5];
    const float* b3  = (const float*)d_in[6];
    const int*   er  = (const int*)d_in[7];
    const int*   ec  = (const int*)d_in[8];
    const float* ev  = (const float*)d_in[9];
    float* out = (float*)d_out;

    static cudaStream_t sA = nullptr, sB = nullptr;
    static cudaEvent_t evRoot = nullptr, evSup = nullptr, evGemm = nullptr, evAgg = nullptr;
    if (!sA) {
        cudaStreamCreateWithFlags(&sA, cudaStreamNonBlocking);
        cudaStreamCreateWithFlags(&sB, cudaStreamNonBlocking);
        cudaEventCreateWithFlags(&evRoot, cudaEventDisableTiming);
        cudaEventCreateWithFlags(&evSup, cudaEventDisableTiming);
        cudaEventCreateWithFlags(&evGemm, cudaEventDisableTiming);
        cudaEventCreateWithFlags(&evAgg, cudaEventDisableTiming);
        cudaFuncSetAttribute(k_gemm, cudaFuncAttributeMaxDynamicSharedMemorySize, SMEM_GEMM);
    }

    // fork from the capture-origin stream
    cudaEventRecord(evRoot, 0);
    cudaStreamWaitEvent(sA, evRoot, 0);
    cudaStreamWaitEvent(sB, evRoot, 0);

    dim3 ggrid(DD / BN, (NN + BM - 1) / BM);

    // --- stream A: conversions + triple GEMM
    k_xh<<<(NN * (DD / 4) + 255) / 256, 256, 0, sA>>>(x);
    k_wh<<<(3 * DD * DD / 4 + 255) / 256, 256, 0, sA>>>(w1, w2, w3);
    k_init<<<(NN + 255) / 256, 256, 0, sB>>>();
    k_gemm<<<ggrid, 256, SMEM_GEMM, sA>>>(0, b2, b3);       // support (fp16)
    cudaEventRecord(evSup, sA);
    // --- stream B: CSR build
    k_hist<<<(EE + 255) / 256, 256, 0, sB>>>(er);
    k_scan<<<1, 1024, 0, sB>>>();
    k_scatter<<<(EE + 255) / 256, 256, 0, sB>>>(er, ec, ev);
    // --- stream A continues with trans/gate GEMMs (overlap with SpMM below)
    k_gemm<<<ggrid, 256, SMEM_GEMM, sA>>>(1, b2, b3);       // trans
    k_gemm<<<ggrid, 256, SMEM_GEMM, sA>>>(2, b2, b3);       // gate
    cudaEventRecord(evGemm, sA);
    // --- stream B: SpMM (needs support + CSR)
    cudaStreamWaitEvent(sB, evSup, 0);
    {
        int warps_per_block = 8;
        int blocks = (NN + warps_per_block - 1) / warps_per_block;
        k_spmm<<<blocks, warps_per_block * 32, 0, sB>>>(b1, out);
    }
    cudaEventRecord(evAgg, sB);

    // --- join on origin stream, final combine
    cudaStreamWaitEvent(0, evGemm, 0);
    cudaStreamWaitEvent(0, evAgg, 0);
    k_combine<<<(NN * (DD / 4) + 255) / 256, 256>>>(out);
}